// round 2
// baseline (speedup 1.0000x reference)
#include <cuda_runtime.h>
#include <cuda_bf16.h>
#include <math.h>

// ---------------- problem constants ----------------
#define BATCH 4096
#define NF    39
#define NE    16
#define NPAIR 741                 // 39*38/2
#define K1    (2 * NPAIR * NE)    // 23712
#define HID   400
#define EPS   1e-5f

// ---------------- scratch (static device globals; no allocation) ----------------
__device__ float d_xcon[(size_t)BATCH * K1];       // 388 MB
__device__ float d_h0[BATCH * HID];
__device__ float d_h1[BATCH * HID];
__device__ float d_h2[BATCH * HID];
__device__ float d_scale[3][HID];
__device__ float d_shift[3][HID];

// =====================================================================
// Kernel 1: gather + SENET + bilinear -> x_con   (one block per batch row)
// =====================================================================
__global__ __launch_bounds__(256) void fuse_front(
    const int* __restrict__ x,      // int32 or int64 (sniffed)
    const float* __restrict__ emb,
    const float* __restrict__ w1, const float* __restrict__ b1,
    const float* __restrict__ w2, const float* __restrict__ b2,
    const float* __restrict__ Wb1, const float* __restrict__ Wb2,
    float* __restrict__ xcon)
{
    __shared__ float xe[NF][NE];
    __shared__ float xs[NF][NE];
    __shared__ float p1[NF][NE];
    __shared__ float p2[NF][NE];
    __shared__ float zf[NF], av[NF], af[NF];
    __shared__ unsigned char ii[NPAIR], jj[NPAIR];
    __shared__ int is64;

    const int b = blockIdx.x;
    const int tid = threadIdx.x;

    if (tid == 0) {
        // If x is int64 (little-endian, values < 1000), every odd 32-bit word
        // of the first row is zero. For int32 the odd words are random in
        // [0,1000) -> probability of all-zero is ~(1/1000)^39.
        int f64 = 1;
        for (int w = 1; w < 2 * NF; w += 2) {
            if (x[w] != 0) { f64 = 0; break; }
        }
        is64 = f64;
    }
    // pair table (i<j), row-major enumeration of triu(1)
    for (int k = tid; k < NPAIR; k += 256) {
        int i = 0, rem = k;
        while (rem >= NF - 1 - i) { rem -= NF - 1 - i; i++; }
        ii[k] = (unsigned char)i;
        jj[k] = (unsigned char)(i + 1 + rem);
    }
    __syncthreads();

    // gather embeddings
    for (int idx = tid; idx < NF * NE; idx += 256) {
        int f = idx >> 4, e = idx & 15;
        int xv = is64 ? x[2 * (b * NF + f)] : x[b * NF + f];
        xe[f][e] = emb[(xv + 1000 * f) * NE + e];
    }
    __syncthreads();

    // z = max over E
    if (tid < NF) {
        float m = xe[tid][0];
        #pragma unroll
        for (int e = 1; e < NE; e++) m = fmaxf(m, xe[tid][e]);
        zf[tid] = m;
    }
    __syncthreads();
    // SENET layer 1: relu(z @ w1.T + b1)
    if (tid < NF) {
        float s = b1[tid];
        for (int j = 0; j < NF; j++) s += zf[j] * w1[tid * NF + j];
        av[tid] = fmaxf(s, 0.0f);
    }
    __syncthreads();
    // SENET layer 2: relu(av @ w2.T + b2)
    if (tid < NF) {
        float s = b2[tid];
        for (int j = 0; j < NF; j++) s += av[j] * w2[tid * NF + j];
        af[tid] = fmaxf(s, 0.0f);
    }
    __syncthreads();

    // projections: p1 = xe @ Wb1^T ; p2 = a * (xe @ Wb2^T) ; xs = a * xe
    for (int idx = tid; idx < NF * NE; idx += 256) {
        int f = idx >> 4, d = idx & 15;
        float s1 = 0.0f, s2 = 0.0f;
        #pragma unroll
        for (int e = 0; e < NE; e++) {
            float v = xe[f][e];
            s1 += v * Wb1[d * NE + e];
            s2 += v * Wb2[d * NE + e];
        }
        p1[f][d] = s1;
        p2[f][d] = af[f] * s2;
        xs[f][d] = af[f] * xe[f][d];
    }
    __syncthreads();

    // interaction products -> x_con row
    float* orow = xcon + (size_t)b * K1;
    for (int idx = tid; idx < NPAIR * NE; idx += 256) {
        int k = idx >> 4, e = idx & 15;
        int i = ii[k], j = jj[k];
        orow[idx]              = p1[i][e] * xe[j][e];
        orow[idx + NPAIR * NE] = p2[i][e] * xs[j][e];
    }
}

// =====================================================================
// Kernel 2: tiled fp32 GEMM   C[m,n] = sum_k f(A[m,k]) * Bw[n,k] + bias[n]
//   f(a) = relu(a*scale[k]+shift[k]) if scale != nullptr, else a
//   Tile: BM=64, BN=128, BK=16, 256 threads, microtile 4x8
// =====================================================================
#define GBM 64
#define GBN 128
#define GBK 16

__global__ __launch_bounds__(256) void gemm_tn(
    const float* __restrict__ A, const float* __restrict__ Bw,
    const float* __restrict__ bias,
    const float* __restrict__ scale, const float* __restrict__ shift,
    float* __restrict__ C, int M, int N, int K)
{
    __shared__ float As[GBK][GBM];
    __shared__ float Bs[GBK][GBN];

    const int tid = threadIdx.x;
    const int nblk = blockIdx.x * GBN;
    const int mblk = blockIdx.y * GBM;

    const int aRow = tid >> 2;       // 0..63
    const int q4   = (tid & 3) * 4;  // k sub-offset 0,4,8,12
    const int ty = tid >> 4;         // 0..15
    const int tx = tid & 15;         // 0..15
    const int m0 = ty * 4;
    const int n0 = tx * 8;

    float acc[4][8];
    #pragma unroll
    for (int i = 0; i < 4; i++)
        #pragma unroll
        for (int j = 0; j < 8; j++) acc[i][j] = 0.0f;

    const bool doTrans = (scale != nullptr);

    for (int k0 = 0; k0 < K; k0 += GBK) {
        // --- load A tile (64x16), apply optional BN+ReLU transform
        {
            float4 va = *(const float4*)(A + (size_t)(mblk + aRow) * K + k0 + q4);
            float e0 = va.x, e1 = va.y, e2 = va.z, e3 = va.w;
            if (doTrans) {
                int gk = k0 + q4;
                e0 = fmaxf(e0 * scale[gk + 0] + shift[gk + 0], 0.0f);
                e1 = fmaxf(e1 * scale[gk + 1] + shift[gk + 1], 0.0f);
                e2 = fmaxf(e2 * scale[gk + 2] + shift[gk + 2], 0.0f);
                e3 = fmaxf(e3 * scale[gk + 3] + shift[gk + 3], 0.0f);
            }
            As[q4 + 0][aRow] = e0;
            As[q4 + 1][aRow] = e1;
            As[q4 + 2][aRow] = e2;
            As[q4 + 3][aRow] = e3;
        }
        // --- load B tile (128x16) with N guard
        #pragma unroll
        for (int r = 0; r < 2; r++) {
            int nl = aRow + r * 64;
            int ng = nblk + nl;
            float4 vb;
            if (ng < N) {
                vb = *(const float4*)(Bw + (size_t)ng * K + k0 + q4);
            } else {
                vb = make_float4(0.f, 0.f, 0.f, 0.f);
            }
            Bs[q4 + 0][nl] = vb.x;
            Bs[q4 + 1][nl] = vb.y;
            Bs[q4 + 2][nl] = vb.z;
            Bs[q4 + 3][nl] = vb.w;
        }
        __syncthreads();

        #pragma unroll
        for (int k = 0; k < GBK; k++) {
            float4 a4 = *(const float4*)(&As[k][m0]);
            float4 b0 = *(const float4*)(&Bs[k][n0]);
            float4 b1v = *(const float4*)(&Bs[k][n0 + 4]);
            float am[4] = {a4.x, a4.y, a4.z, a4.w};
            float bn[8] = {b0.x, b0.y, b0.z, b0.w, b1v.x, b1v.y, b1v.z, b1v.w};
            #pragma unroll
            for (int i = 0; i < 4; i++)
                #pragma unroll
                for (int j = 0; j < 8; j++)
                    acc[i][j] = fmaf(am[i], bn[j], acc[i][j]);
        }
        __syncthreads();
    }

    // epilogue: +bias, store with N guard
    #pragma unroll
    for (int i = 0; i < 4; i++) {
        int row = mblk + m0 + i;
        #pragma unroll
        for (int j = 0; j < 8; j++) {
            int ng = nblk + n0 + j;
            if (ng < N) C[(size_t)row * N + ng] = acc[i][j] + bias[ng];
        }
    }
}

// =====================================================================
// Kernel 3: batchnorm stats per column -> folded scale/shift
// =====================================================================
__global__ __launch_bounds__(128) void bn_stats(
    const float* __restrict__ h, const float* __restrict__ g,
    const float* __restrict__ be, float* __restrict__ scale,
    float* __restrict__ shift, int Mrows, int N)
{
    __shared__ double ssum[128];
    __shared__ double ssq[128];
    const int col = blockIdx.x;
    const int tid = threadIdx.x;
    double s = 0.0, s2 = 0.0;
    for (int r = tid; r < Mrows; r += 128) {
        double v = (double)h[(size_t)r * N + col];
        s += v;
        s2 += v * v;
    }
    ssum[tid] = s; ssq[tid] = s2;
    __syncthreads();
    for (int off = 64; off > 0; off >>= 1) {
        if (tid < off) { ssum[tid] += ssum[tid + off]; ssq[tid] += ssq[tid + off]; }
        __syncthreads();
    }
    if (tid == 0) {
        double mu = ssum[0] / Mrows;
        double var = ssq[0] / Mrows - mu * mu;
        float rstd = (float)(1.0 / sqrt(var + (double)EPS));
        float sc = g[col] * rstd;
        scale[col] = sc;
        shift[col] = be[col] - (float)mu * sc;
    }
}

// =====================================================================
// Kernel 4: final dot  out[b] = sum_k relu(h[b,k]*scale[k]+shift[k]) * w3[k] + b3
// =====================================================================
__global__ __launch_bounds__(256) void final_dot(
    const float* __restrict__ h, const float* __restrict__ scale,
    const float* __restrict__ shift, const float* __restrict__ w3,
    const float* __restrict__ b3, float* __restrict__ out)
{
    const int gtid = blockIdx.x * blockDim.x + threadIdx.x;
    const int warp = gtid >> 5;
    const int lane = gtid & 31;
    if (warp >= BATCH) return;
    float s = 0.0f;
    for (int k = lane; k < HID; k += 32) {
        float v = fmaxf(h[(size_t)warp * HID + k] * scale[k] + shift[k], 0.0f);
        s += v * w3[k];
    }
    #pragma unroll
    for (int off = 16; off > 0; off >>= 1)
        s += __shfl_down_sync(0xFFFFFFFFu, s, off);
    if (lane == 0) out[warp] = s + b3[0];
}

// =====================================================================
// launcher
// =====================================================================
extern "C" void kernel_launch(void* const* d_in, const int* in_sizes, int n_in,
                              void* d_out, int out_size)
{
    const int*   x    = (const int*)  d_in[0];
    const float* emb  = (const float*)d_in[1];
    const float* sw1  = (const float*)d_in[2];
    const float* sb1  = (const float*)d_in[3];
    const float* sw2  = (const float*)d_in[4];
    const float* sb2  = (const float*)d_in[5];
    const float* Wb1  = (const float*)d_in[6];
    const float* Wb2  = (const float*)d_in[7];
    const float* mw0  = (const float*)d_in[8];
    const float* mb0  = (const float*)d_in[9];
    const float* g0   = (const float*)d_in[10];
    const float* be0  = (const float*)d_in[11];
    const float* mw1  = (const float*)d_in[12];
    const float* mb1  = (const float*)d_in[13];
    const float* g1   = (const float*)d_in[14];
    const float* be1  = (const float*)d_in[15];
    const float* mw2  = (const float*)d_in[16];
    const float* mb2  = (const float*)d_in[17];
    const float* g2   = (const float*)d_in[18];
    const float* be2  = (const float*)d_in[19];
    const float* mw3  = (const float*)d_in[20];
    const float* mb3  = (const float*)d_in[21];
    float* out = (float*)d_out;

    float *xcon, *h0, *h1, *h2, *sc, *sh;
    cudaGetSymbolAddress((void**)&xcon, d_xcon);
    cudaGetSymbolAddress((void**)&h0, d_h0);
    cudaGetSymbolAddress((void**)&h1, d_h1);
    cudaGetSymbolAddress((void**)&h2, d_h2);
    cudaGetSymbolAddress((void**)&sc, d_scale);
    cudaGetSymbolAddress((void**)&sh, d_shift);

    // 1) front end -> x_con
    fuse_front<<<BATCH, 256>>>(x, emb, sw1, sb1, sw2, sb2, Wb1, Wb2, xcon);

    // 2) GEMM0: h0 = x_con @ mw0^T + mb0
    {
        dim3 grid((HID + GBN - 1) / GBN, BATCH / GBM);
        gemm_tn<<<grid, 256>>>(xcon, mw0, mb0, nullptr, nullptr, h0,
                               BATCH, HID, K1);
    }
    // BN0 stats
    bn_stats<<<HID, 128>>>(h0, g0, be0, sc + 0 * HID, sh + 0 * HID, BATCH, HID);

    // 3) GEMM1 (A transformed by BN0+ReLU): h1 = f(h0) @ mw1^T + mb1
    {
        dim3 grid((HID + GBN - 1) / GBN, BATCH / GBM);
        gemm_tn<<<grid, 256>>>(h0, mw1, mb1, sc + 0 * HID, sh + 0 * HID, h1,
                               BATCH, HID, HID);
    }
    bn_stats<<<HID, 128>>>(h1, g1, be1, sc + 1 * HID, sh + 1 * HID, BATCH, HID);

    // 4) GEMM2: h2 = f(h1) @ mw2^T + mb2
    {
        dim3 grid((HID + GBN - 1) / GBN, BATCH / GBM);
        gemm_tn<<<grid, 256>>>(h1, mw2, mb2, sc + 1 * HID, sh + 1 * HID, h2,
                               BATCH, HID, HID);
    }
    bn_stats<<<HID, 128>>>(h2, g2, be2, sc + 2 * HID, sh + 2 * HID, BATCH, HID);

    // 5) final dot: out = f(h2) @ mw3^T + mb3
    final_dot<<<(BATCH * 32 + 255) / 256, 256>>>(h2, sc + 2 * HID, sh + 2 * HID,
                                                 mw3, mb3, out);
}

// round 4
// speedup vs baseline: 3.4520x; 3.4520x over previous
#include <cuda_runtime.h>
#include <cuda_bf16.h>
#include <math.h>
#include <stdint.h>

// ---------------- problem constants ----------------
#define BATCH 4096
#define NF    39
#define NE    16
#define NPAIR 741                 // 39*38/2
#define K1    (2 * NPAIR * NE)    // 23712
#define HID   400
#define EPS   1e-5f

// ---------------- GEMM0 (mma.sync bf16 3x-split) config ----------------
#define G0_BM 128
#define G0_BN 80
#define G0_BK 32                  // halves per k-tile
#define G0_NTILES 741             // K1 / 32
#define G0_T0SPLIT 371            // kseg0: tiles [0,371), kseg1: [371,741)

// smem: padded row stride 40 halves = 80 bytes
#define A_ROWB   80
#define OFF_ALO  10240            // 128 rows * 80B
#define OFF_BHI  20480
#define OFF_BLO  26880            // +80*80
#define STAGE    33280            // 26880 + 6400
#define NSTAGE   3
#define SMEM_G0  (STAGE * NSTAGE) // 99840

// ---------------- scratch (static device globals; no allocation) ----------------
__device__ __nv_bfloat16 d_a_hi[(size_t)BATCH * K1];   // 194 MB
__device__ __nv_bfloat16 d_a_lo[(size_t)BATCH * K1];   // 194 MB
__device__ __nv_bfloat16 d_b_hi[(size_t)HID * K1];     // 19 MB
__device__ __nv_bfloat16 d_b_lo[(size_t)HID * K1];     // 19 MB
__device__ float d_part[2 * (size_t)BATCH * HID];      // split-K partials
__device__ float d_h0[BATCH * HID];
__device__ float d_h1[BATCH * HID];
__device__ float d_h2[BATCH * HID];
__device__ float d_scale[3][HID];
__device__ float d_shift[3][HID];

// ---------------- helpers ----------------
__device__ __forceinline__ uint32_t smem_u32(const void* p) {
    uint32_t a;
    asm("{ .reg .u64 t; cvta.to.shared.u64 t, %1; cvt.u32.u64 %0, t; }" : "=r"(a) : "l"(p));
    return a;
}

#define CP_ASYNC16(dst, src) \
    asm volatile("cp.async.cg.shared.global [%0], [%1], 16;" :: "r"(dst), "l"(src))
#define CP_COMMIT() asm volatile("cp.async.commit_group;" ::: "memory")
#define CP_WAIT1()  asm volatile("cp.async.wait_group 1;" ::: "memory")
#define CP_WAIT0()  asm volatile("cp.async.wait_group 0;" ::: "memory")

__device__ __forceinline__ void mma_bf16(float* c, const uint32_t* a, const uint32_t* b) {
    asm volatile(
        "mma.sync.aligned.m16n8k16.row.col.f32.bf16.bf16.f32 "
        "{%0,%1,%2,%3}, {%4,%5,%6,%7}, {%8,%9}, {%0,%1,%2,%3};"
        : "+f"(c[0]), "+f"(c[1]), "+f"(c[2]), "+f"(c[3])
        : "r"(a[0]), "r"(a[1]), "r"(a[2]), "r"(a[3]), "r"(b[0]), "r"(b[1]));
}

// =====================================================================
// Kernel 1: gather + SENET + bilinear -> A_hi / A_lo (bf16 split)
// =====================================================================
__global__ __launch_bounds__(256) void fuse_front(
    const int* __restrict__ x,
    const float* __restrict__ emb,
    const float* __restrict__ w1, const float* __restrict__ b1,
    const float* __restrict__ w2, const float* __restrict__ b2,
    const float* __restrict__ Wb1, const float* __restrict__ Wb2,
    __nv_bfloat16* __restrict__ a_hi, __nv_bfloat16* __restrict__ a_lo)
{
    __shared__ float xe[NF][NE];
    __shared__ float xs[NF][NE];
    __shared__ float p1[NF][NE];
    __shared__ float p2[NF][NE];
    __shared__ float zf[NF], av[NF], af[NF];
    __shared__ unsigned char ii[NPAIR], jj[NPAIR];
    __shared__ int is64;

    const int b = blockIdx.x;
    const int tid = threadIdx.x;

    if (tid == 0) {
        int f64 = 1;
        for (int w = 1; w < 2 * NF; w += 2)
            if (x[w] != 0) { f64 = 0; break; }
        is64 = f64;
    }
    for (int k = tid; k < NPAIR; k += 256) {
        int i = 0, rem = k;
        while (rem >= NF - 1 - i) { rem -= NF - 1 - i; i++; }
        ii[k] = (unsigned char)i;
        jj[k] = (unsigned char)(i + 1 + rem);
    }
    __syncthreads();

    for (int idx = tid; idx < NF * NE; idx += 256) {
        int f = idx >> 4, e = idx & 15;
        int xv = is64 ? x[2 * (b * NF + f)] : x[b * NF + f];
        xe[f][e] = emb[(xv + 1000 * f) * NE + e];
    }
    __syncthreads();

    if (tid < NF) {
        float m = xe[tid][0];
        #pragma unroll
        for (int e = 1; e < NE; e++) m = fmaxf(m, xe[tid][e]);
        zf[tid] = m;
    }
    __syncthreads();
    if (tid < NF) {
        float s = b1[tid];
        for (int j = 0; j < NF; j++) s += zf[j] * w1[tid * NF + j];
        av[tid] = fmaxf(s, 0.0f);
    }
    __syncthreads();
    if (tid < NF) {
        float s = b2[tid];
        for (int j = 0; j < NF; j++) s += av[j] * w2[tid * NF + j];
        af[tid] = fmaxf(s, 0.0f);
    }
    __syncthreads();

    for (int idx = tid; idx < NF * NE; idx += 256) {
        int f = idx >> 4, d = idx & 15;
        float s1 = 0.0f, s2 = 0.0f;
        #pragma unroll
        for (int e = 0; e < NE; e++) {
            float v = xe[f][e];
            s1 += v * Wb1[d * NE + e];
            s2 += v * Wb2[d * NE + e];
        }
        p1[f][d] = s1;
        p2[f][d] = af[f] * s2;
        xs[f][d] = af[f] * xe[f][d];
    }
    __syncthreads();

    __nv_bfloat16* ohi = a_hi + (size_t)b * K1;
    __nv_bfloat16* olo = a_lo + (size_t)b * K1;
    for (int idx = tid; idx < NPAIR * NE; idx += 256) {
        int k = idx >> 4, e = idx & 15;
        int i = ii[k], j = jj[k];
        float v1 = p1[i][e] * xe[j][e];
        float v2 = p2[i][e] * xs[j][e];
        __nv_bfloat16 h1 = __float2bfloat16(v1);
        __nv_bfloat16 h2 = __float2bfloat16(v2);
        ohi[idx] = h1;
        olo[idx] = __float2bfloat16(v1 - __bfloat162float(h1));
        ohi[idx + NPAIR * NE] = h2;
        olo[idx + NPAIR * NE] = __float2bfloat16(v2 - __bfloat162float(h2));
    }
}

// =====================================================================
// Kernel 1b: split mw0 into bf16 hi/lo
// =====================================================================
__global__ __launch_bounds__(256) void split_b(
    const float* __restrict__ w, __nv_bfloat16* __restrict__ hi,
    __nv_bfloat16* __restrict__ lo)
{
    size_t i = (size_t)blockIdx.x * 256 + threadIdx.x;
    size_t n = (size_t)HID * K1;
    if (i < n) {
        float v = w[i];
        __nv_bfloat16 h = __float2bfloat16(v);
        hi[i] = h;
        lo[i] = __float2bfloat16(v - __bfloat162float(h));
    }
}

// =====================================================================
// Kernel 2: GEMM0 via mma.sync bf16 (3-product split), split-K=2
//   part[kseg, m, n] = sum_{k in seg} A[m,k] * B[n,k]
//   CTA tile 128x80, BK=32, 8 warps (4m x 2n), warp tile 32x40
// =====================================================================
__global__ __launch_bounds__(256, 1) void gemm0_mma(
    const __nv_bfloat16* __restrict__ a_hi, const __nv_bfloat16* __restrict__ a_lo,
    const __nv_bfloat16* __restrict__ b_hi, const __nv_bfloat16* __restrict__ b_lo,
    float* __restrict__ part)
{
    extern __shared__ char smem[];
    const uint32_t sb = smem_u32(smem);
    const int tid  = threadIdx.x;
    const int wid  = tid >> 5;
    const int lane = tid & 31;

    const int nbase = blockIdx.x * G0_BN;
    const int mbase = blockIdx.y * G0_BM;
    const int kseg  = blockIdx.z;
    const int t0 = (kseg == 0) ? 0 : G0_T0SPLIT;
    const int t1 = (kseg == 0) ? G0_T0SPLIT : G0_NTILES;
    const int T = t1 - t0;

    const int wm = (wid & 3) * 32;   // warp m origin within tile
    const int wn = (wid >> 2) * 40;  // warp n origin within tile
    const int grp = lane >> 2;       // 0..7
    const int q   = lane & 3;        // 0..3

    float acc[2][5][4];
    #pragma unroll
    for (int im = 0; im < 2; im++)
        #pragma unroll
        for (int in = 0; in < 5; in++)
            #pragma unroll
            for (int r = 0; r < 4; r++) acc[im][in][r] = 0.0f;

    // ---- async tile loader (all 256 threads) ----
    auto load_tile = [&](int s, int t) {
        const int k0 = t * G0_BK;            // in halves
        const uint32_t st = sb + s * STAGE;
        #pragma unroll
        for (int idx = tid; idx < 512; idx += 256) {   // A: 128 rows x 4 chunks
            int r = idx >> 2, ch = idx & 3;
            uint32_t dst = st + r * A_ROWB + ch * 16;
            size_t g = (size_t)(mbase + r) * K1 + k0 + ch * 8;
            CP_ASYNC16(dst, a_hi + g);
            CP_ASYNC16(dst + OFF_ALO, a_lo + g);
        }
        #pragma unroll
        for (int idx = tid; idx < 320; idx += 256) {   // B: 80 rows x 4 chunks
            int r = idx >> 2, ch = idx & 3;
            uint32_t dst = st + OFF_BHI + r * A_ROWB + ch * 16;
            size_t g = (size_t)(nbase + r) * K1 + k0 + ch * 8;
            CP_ASYNC16(dst, b_hi + g);
            CP_ASYNC16(dst + 6400, b_lo + g);
        }
        CP_COMMIT();
    };

    // prologue (T >= 2 always: 370/371 tiles)
    load_tile(0, t0);
    load_tile(1, t0 + 1);

    for (int u = 0; u < T; ++u) {
        if (u < T - 1) { CP_WAIT1(); } else { CP_WAIT0(); }
        __syncthreads();

        // prefetch stage u+2 (overwrites stage used by compute u-1; safe post-barrier)
        if (u + 2 < T) load_tile((u + 2) % NSTAGE, t0 + u + 2);

        // ---- compute on stage u%3 ----
        const char* As = smem + (u % NSTAGE) * STAGE;
        const char* Bs = As + OFF_BHI;

        #pragma unroll
        for (int kstep = 0; kstep < 2; kstep++) {
            const int kh = kstep * 16 + q * 2;   // half index within 32

            uint32_t ah[2][4], al[2][4];
            #pragma unroll
            for (int im = 0; im < 2; im++) {
                const char* p = As + (wm + im * 16 + grp) * A_ROWB + kh * 2;
                ah[im][0] = *(const uint32_t*)(p);
                ah[im][1] = *(const uint32_t*)(p + 8 * A_ROWB);
                ah[im][2] = *(const uint32_t*)(p + 16);
                ah[im][3] = *(const uint32_t*)(p + 8 * A_ROWB + 16);
                al[im][0] = *(const uint32_t*)(p + OFF_ALO);
                al[im][1] = *(const uint32_t*)(p + OFF_ALO + 8 * A_ROWB);
                al[im][2] = *(const uint32_t*)(p + OFF_ALO + 16);
                al[im][3] = *(const uint32_t*)(p + OFF_ALO + 8 * A_ROWB + 16);
            }
            uint32_t bh[5][2], bl[5][2];
            #pragma unroll
            for (int in = 0; in < 5; in++) {
                const char* p = Bs + (wn + in * 8 + grp) * A_ROWB + kh * 2;
                bh[in][0] = *(const uint32_t*)(p);
                bh[in][1] = *(const uint32_t*)(p + 16);
                bl[in][0] = *(const uint32_t*)(p + 6400);
                bl[in][1] = *(const uint32_t*)(p + 6400 + 16);
            }
            #pragma unroll
            for (int im = 0; im < 2; im++)
                #pragma unroll
                for (int in = 0; in < 5; in++) {
                    mma_bf16(acc[im][in], ah[im], bh[in]);
                    mma_bf16(acc[im][in], ah[im], bl[in]);
                    mma_bf16(acc[im][in], al[im], bh[in]);
                }
        }
        __syncthreads();
    }

    // ---- epilogue: write fp32 partials ----
    #pragma unroll
    for (int im = 0; im < 2; im++) {
        #pragma unroll
        for (int in = 0; in < 5; in++) {
            int row = mbase + wm + im * 16 + grp;
            int col = nbase + wn + in * 8 + q * 2;
            float* d = part + ((size_t)kseg * BATCH + row) * HID + col;
            *(float2*)d = make_float2(acc[im][in][0], acc[im][in][1]);
            *(float2*)(d + 8 * HID) = make_float2(acc[im][in][2], acc[im][in][3]);
        }
    }
}

// =====================================================================
// Kernel 2b: reduce split-K partials + bias -> h0
// =====================================================================
__global__ __launch_bounds__(256) void reduce_h0(
    const float* __restrict__ part, const float* __restrict__ bias,
    float* __restrict__ h0)
{
    const size_t stride = (size_t)BATCH * HID;
    size_t i4 = (size_t)blockIdx.x * 256 + threadIdx.x;
    if (i4 >= stride / 4) return;
    float4 p0 = *(const float4*)(part + i4 * 4);
    float4 p1 = *(const float4*)(part + stride + i4 * 4);
    int c = (int)((i4 * 4) % HID);
    float4 r;
    r.x = p0.x + p1.x + bias[c + 0];
    r.y = p0.y + p1.y + bias[c + 1];
    r.z = p0.z + p1.z + bias[c + 2];
    r.w = p0.w + p1.w + bias[c + 3];
    *(float4*)(h0 + i4 * 4) = r;
}

// =====================================================================
// Kernel 3: tiled fp32 GEMM for small layers (fused BN+ReLU on A)
// =====================================================================
#define GBM 64
#define GBN 128
#define GBK 16

__global__ __launch_bounds__(256) void gemm_tn(
    const float* __restrict__ A, const float* __restrict__ Bw,
    const float* __restrict__ bias,
    const float* __restrict__ scale, const float* __restrict__ shift,
    float* __restrict__ C, int M, int N, int K)
{
    __shared__ float As[GBK][GBM];
    __shared__ float Bs[GBK][GBN];

    const int tid = threadIdx.x;
    const int nblk = blockIdx.x * GBN;
    const int mblk = blockIdx.y * GBM;

    const int aRow = tid >> 2;
    const int q4   = (tid & 3) * 4;
    const int ty = tid >> 4;
    const int tx = tid & 15;
    const int m0 = ty * 4;
    const int n0 = tx * 8;

    float acc[4][8];
    #pragma unroll
    for (int i = 0; i < 4; i++)
        #pragma unroll
        for (int j = 0; j < 8; j++) acc[i][j] = 0.0f;

    const bool doTrans = (scale != nullptr);

    for (int k0 = 0; k0 < K; k0 += GBK) {
        {
            float4 va = *(const float4*)(A + (size_t)(mblk + aRow) * K + k0 + q4);
            float e0 = va.x, e1 = va.y, e2 = va.z, e3 = va.w;
            if (doTrans) {
                int gk = k0 + q4;
                e0 = fmaxf(e0 * scale[gk + 0] + shift[gk + 0], 0.0f);
                e1 = fmaxf(e1 * scale[gk + 1] + shift[gk + 1], 0.0f);
                e2 = fmaxf(e2 * scale[gk + 2] + shift[gk + 2], 0.0f);
                e3 = fmaxf(e3 * scale[gk + 3] + shift[gk + 3], 0.0f);
            }
            As[q4 + 0][aRow] = e0;
            As[q4 + 1][aRow] = e1;
            As[q4 + 2][aRow] = e2;
            As[q4 + 3][aRow] = e3;
        }
        #pragma unroll
        for (int r = 0; r < 2; r++) {
            int nl = aRow + r * 64;
            int ng = nblk + nl;
            float4 vb;
            if (ng < N) vb = *(const float4*)(Bw + (size_t)ng * K + k0 + q4);
            else        vb = make_float4(0.f, 0.f, 0.f, 0.f);
            Bs[q4 + 0][nl] = vb.x;
            Bs[q4 + 1][nl] = vb.y;
            Bs[q4 + 2][nl] = vb.z;
            Bs[q4 + 3][nl] = vb.w;
        }
        __syncthreads();

        #pragma unroll
        for (int k = 0; k < GBK; k++) {
            float4 a4 = *(const float4*)(&As[k][m0]);
            float4 b0 = *(const float4*)(&Bs[k][n0]);
            float4 b1v = *(const float4*)(&Bs[k][n0 + 4]);
            float am[4] = {a4.x, a4.y, a4.z, a4.w};
            float bn[8] = {b0.x, b0.y, b0.z, b0.w, b1v.x, b1v.y, b1v.z, b1v.w};
            #pragma unroll
            for (int i = 0; i < 4; i++)
                #pragma unroll
                for (int j = 0; j < 8; j++)
                    acc[i][j] = fmaf(am[i], bn[j], acc[i][j]);
        }
        __syncthreads();
    }

    #pragma unroll
    for (int i = 0; i < 4; i++) {
        int row = mblk + m0 + i;
        #pragma unroll
        for (int j = 0; j < 8; j++) {
            int ng = nblk + n0 + j;
            if (ng < N) C[(size_t)row * N + ng] = acc[i][j] + bias[ng];
        }
    }
}

// =====================================================================
// Kernel 4: batchnorm stats per column -> folded scale/shift
// =====================================================================
__global__ __launch_bounds__(128) void bn_stats(
    const float* __restrict__ h, const float* __restrict__ g,
    const float* __restrict__ be, float* __restrict__ scale,
    float* __restrict__ shift, int Mrows, int N)
{
    __shared__ double ssum[128];
    __shared__ double ssq[128];
    const int col = blockIdx.x;
    const int tid = threadIdx.x;
    double s = 0.0, s2 = 0.0;
    for (int r = tid; r < Mrows; r += 128) {
        double v = (double)h[(size_t)r * N + col];
        s += v;
        s2 += v * v;
    }
    ssum[tid] = s; ssq[tid] = s2;
    __syncthreads();
    for (int off = 64; off > 0; off >>= 1) {
        if (tid < off) { ssum[tid] += ssum[tid + off]; ssq[tid] += ssq[tid + off]; }
        __syncthreads();
    }
    if (tid == 0) {
        double mu = ssum[0] / Mrows;
        double var = ssq[0] / Mrows - mu * mu;
        float rstd = (float)(1.0 / sqrt(var + (double)EPS));
        float sc = g[col] * rstd;
        scale[col] = sc;
        shift[col] = be[col] - (float)mu * sc;
    }
}

// =====================================================================
// Kernel 5: final dot
// =====================================================================
__global__ __launch_bounds__(256) void final_dot(
    const float* __restrict__ h, const float* __restrict__ scale,
    const float* __restrict__ shift, const float* __restrict__ w3,
    const float* __restrict__ b3, float* __restrict__ out)
{
    const int gtid = blockIdx.x * blockDim.x + threadIdx.x;
    const int warp = gtid >> 5;
    const int lane = gtid & 31;
    if (warp >= BATCH) return;
    float s = 0.0f;
    for (int k = lane; k < HID; k += 32) {
        float v = fmaxf(h[(size_t)warp * HID + k] * scale[k] + shift[k], 0.0f);
        s += v * w3[k];
    }
    #pragma unroll
    for (int off = 16; off > 0; off >>= 1)
        s += __shfl_down_sync(0xFFFFFFFFu, s, off);
    if (lane == 0) out[warp] = s + b3[0];
}

// =====================================================================
// launcher
// =====================================================================
extern "C" void kernel_launch(void* const* d_in, const int* in_sizes, int n_in,
                              void* d_out, int out_size)
{
    const int*   x    = (const int*)  d_in[0];
    const float* emb  = (const float*)d_in[1];
    const float* sw1  = (const float*)d_in[2];
    const float* sb1  = (const float*)d_in[3];
    const float* sw2  = (const float*)d_in[4];
    const float* sb2  = (const float*)d_in[5];
    const float* Wb1  = (const float*)d_in[6];
    const float* Wb2  = (const float*)d_in[7];
    const float* mw0  = (const float*)d_in[8];
    const float* mb0  = (const float*)d_in[9];
    const float* g0   = (const float*)d_in[10];
    const float* be0  = (const float*)d_in[11];
    const float* mw1  = (const float*)d_in[12];
    const float* mb1  = (const float*)d_in[13];
    const float* g1   = (const float*)d_in[14];
    const float* be1  = (const float*)d_in[15];
    const float* mw2  = (const float*)d_in[16];
    const float* mb2  = (const float*)d_in[17];
    const float* g2   = (const float*)d_in[18];
    const float* be2  = (const float*)d_in[19];
    const float* mw3  = (const float*)d_in[20];
    const float* mb3  = (const float*)d_in[21];
    float* out = (float*)d_out;

    __nv_bfloat16 *a_hi, *a_lo, *b_hi, *b_lo;
    float *part, *h0, *h1, *h2, *sc, *sh;
    cudaGetSymbolAddress((void**)&a_hi, d_a_hi);
    cudaGetSymbolAddress((void**)&a_lo, d_a_lo);
    cudaGetSymbolAddress((void**)&b_hi, d_b_hi);
    cudaGetSymbolAddress((void**)&b_lo, d_b_lo);
    cudaGetSymbolAddress((void**)&part, d_part);
    cudaGetSymbolAddress((void**)&h0, d_h0);
    cudaGetSymbolAddress((void**)&h1, d_h1);
    cudaGetSymbolAddress((void**)&h2, d_h2);
    cudaGetSymbolAddress((void**)&sc, d_scale);
    cudaGetSymbolAddress((void**)&sh, d_shift);

    static int smem_set = 0;
    if (!smem_set) {
        cudaFuncSetAttribute(gemm0_mma, cudaFuncAttributeMaxDynamicSharedMemorySize,
                             SMEM_G0);
        smem_set = 1;
    }

    // 1) front end -> A hi/lo (bf16); weight split
    fuse_front<<<BATCH, 256>>>(x, emb, sw1, sb1, sw2, sb2, Wb1, Wb2, a_hi, a_lo);
    {
        size_t n = (size_t)HID * K1;
        split_b<<<(unsigned)((n + 255) / 256), 256>>>(mw0, b_hi, b_lo);
    }

    // 2) GEMM0 (mma.sync bf16 3x, split-K=2) + reduce
    {
        dim3 grid(HID / G0_BN, BATCH / G0_BM, 2);   // (5, 32, 2) = 320 CTAs
        gemm0_mma<<<grid, 256, SMEM_G0>>>(a_hi, a_lo, b_hi, b_lo, part);
        size_t n4 = (size_t)BATCH * HID / 4;
        reduce_h0<<<(unsigned)((n4 + 255) / 256), 256>>>(part, mb0, h0);
    }
    bn_stats<<<HID, 128>>>(h0, g0, be0, sc + 0 * HID, sh + 0 * HID, BATCH, HID);

    // 3) GEMM1: h1 = relu(bn(h0)) @ mw1^T + mb1
    {
        dim3 grid((HID + GBN - 1) / GBN, BATCH / GBM);
        gemm_tn<<<grid, 256>>>(h0, mw1, mb1, sc + 0 * HID, sh + 0 * HID, h1,
                               BATCH, HID, HID);
    }
    bn_stats<<<HID, 128>>>(h1, g1, be1, sc + 1 * HID, sh + 1 * HID, BATCH, HID);

    // 4) GEMM2
    {
        dim3 grid((HID + GBN - 1) / GBN, BATCH / GBM);
        gemm_tn<<<grid, 256>>>(h1, mw2, mb2, sc + 1 * HID, sh + 1 * HID, h2,
                               BATCH, HID, HID);
    }
    bn_stats<<<HID, 128>>>(h2, g2, be2, sc + 2 * HID, sh + 2 * HID, BATCH, HID);

    // 5) final dot
    final_dot<<<(BATCH * 32 + 255) / 256, 256>>>(h2, sc + 2 * HID, sh + 2 * HID,
                                                 mw3, mb3, out);
}

// round 5
// speedup vs baseline: 4.3489x; 1.2598x over previous
#include <cuda_runtime.h>
#include <cuda_bf16.h>
#include <math.h>
#include <stdint.h>

// ---------------- problem constants ----------------
#define BATCH 4096
#define NF    39
#define NE    16
#define NPAIR 741
#define K1    (2 * NPAIR * NE)    // 23712
#define HID   400
#define K2P   416                 // HID padded to multiple of 32
#define EPS   1e-5f

// ---------------- bf16 3x GEMM tiling ----------------
#define BM 128
#define BN 80
#define BK 32                     // halves per k-tile (64 bytes)
#define A_ROWB 80                 // smem row stride bytes (32 halves + 8 pad)
#define OFF_ALO 10240             // 128*80
#define OFF_BHI 20480
#define OFF_BLO 26880             // +80*80
#define STAGE   33280
#define NSTAGE  4
#define SMEM_G  (STAGE * NSTAGE)  // 133120
#define KSPLIT0 8
#define SQOFF   (HID * 128)       // 51200

// ---------------- scratch (static device globals) ----------------
__device__ __nv_bfloat16 d_a_hi[(size_t)BATCH * K1];
__device__ __nv_bfloat16 d_a_lo[(size_t)BATCH * K1];
__device__ __nv_bfloat16 d_b_hi[(size_t)HID * K1];
__device__ __nv_bfloat16 d_b_lo[(size_t)HID * K1];
__device__ __nv_bfloat16 d_a2_hi[(size_t)BATCH * K2P];
__device__ __nv_bfloat16 d_a2_lo[(size_t)BATCH * K2P];
__device__ __nv_bfloat16 d_w2_hi[(size_t)HID * K2P];
__device__ __nv_bfloat16 d_w2_lo[(size_t)HID * K2P];
__device__ float d_part[(size_t)KSPLIT0 * BATCH * HID];
__device__ float d_h0[BATCH * HID];
__device__ float d_h1[BATCH * HID];
__device__ float d_h2[BATCH * HID];
__device__ float d_pstat[2 * 128 * HID];
__device__ float d_scale[3][HID];
__device__ float d_shift[3][HID];

// ---------------- helpers ----------------
__device__ __forceinline__ uint32_t smem_u32(const void* p) {
    uint32_t a;
    asm("{ .reg .u64 t; cvta.to.shared.u64 t, %1; cvt.u32.u64 %0, t; }" : "=r"(a) : "l"(p));
    return a;
}

#define CP_ASYNC16(dst, src) \
    asm volatile("cp.async.cg.shared.global [%0], [%1], 16;" :: "r"(dst), "l"(src))
#define CP_COMMIT() asm volatile("cp.async.commit_group;" ::: "memory")
#define CP_WAIT2()  asm volatile("cp.async.wait_group 2;" ::: "memory")
#define CP_WAIT1()  asm volatile("cp.async.wait_group 1;" ::: "memory")
#define CP_WAIT0()  asm volatile("cp.async.wait_group 0;" ::: "memory")

#define LDSM4(r0, r1, r2, r3, a) \
    asm volatile("ldmatrix.sync.aligned.m8n8.x4.shared.b16 {%0,%1,%2,%3}, [%4];" \
        : "=r"(r0), "=r"(r1), "=r"(r2), "=r"(r3) : "r"(a))
#define LDSM2(r0, r1, a) \
    asm volatile("ldmatrix.sync.aligned.m8n8.x2.shared.b16 {%0,%1}, [%2];" \
        : "=r"(r0), "=r"(r1) : "r"(a))

__device__ __forceinline__ void mma_bf16(float* c, const uint32_t* a, const uint32_t* b) {
    asm volatile(
        "mma.sync.aligned.m16n8k16.row.col.f32.bf16.bf16.f32 "
        "{%0,%1,%2,%3}, {%4,%5,%6,%7}, {%8,%9}, {%0,%1,%2,%3};"
        : "+f"(c[0]), "+f"(c[1]), "+f"(c[2]), "+f"(c[3])
        : "r"(a[0]), "r"(a[1]), "r"(a[2]), "r"(a[3]), "r"(b[0]), "r"(b[1]));
}

// =====================================================================
// Kernel 1: gather + SENET + bilinear -> A_hi / A_lo (bf16 split)
// =====================================================================
__global__ __launch_bounds__(256) void fuse_front(
    const int* __restrict__ x,
    const float* __restrict__ emb,
    const float* __restrict__ w1, const float* __restrict__ b1,
    const float* __restrict__ w2, const float* __restrict__ b2,
    const float* __restrict__ Wb1, const float* __restrict__ Wb2,
    __nv_bfloat16* __restrict__ a_hi, __nv_bfloat16* __restrict__ a_lo)
{
    __shared__ float xe[NF][NE];
    __shared__ float xs[NF][NE];
    __shared__ float p1[NF][NE];
    __shared__ float p2[NF][NE];
    __shared__ float zf[NF], av[NF], af[NF];
    __shared__ unsigned char ii[NPAIR], jj[NPAIR];
    __shared__ int is64;

    const int b = blockIdx.x;
    const int tid = threadIdx.x;

    if (tid == 0) {
        int f64 = 1;
        for (int w = 1; w < 2 * NF; w += 2)
            if (x[w] != 0) { f64 = 0; break; }
        is64 = f64;
    }
    for (int k = tid; k < NPAIR; k += 256) {
        int i = 0, rem = k;
        while (rem >= NF - 1 - i) { rem -= NF - 1 - i; i++; }
        ii[k] = (unsigned char)i;
        jj[k] = (unsigned char)(i + 1 + rem);
    }
    __syncthreads();

    for (int idx = tid; idx < NF * NE; idx += 256) {
        int f = idx >> 4, e = idx & 15;
        int xv = is64 ? x[2 * (b * NF + f)] : x[b * NF + f];
        xe[f][e] = emb[(xv + 1000 * f) * NE + e];
    }
    __syncthreads();

    if (tid < NF) {
        float m = xe[tid][0];
        #pragma unroll
        for (int e = 1; e < NE; e++) m = fmaxf(m, xe[tid][e]);
        zf[tid] = m;
    }
    __syncthreads();
    if (tid < NF) {
        float s = b1[tid];
        for (int j = 0; j < NF; j++) s += zf[j] * w1[tid * NF + j];
        av[tid] = fmaxf(s, 0.0f);
    }
    __syncthreads();
    if (tid < NF) {
        float s = b2[tid];
        for (int j = 0; j < NF; j++) s += av[j] * w2[tid * NF + j];
        af[tid] = fmaxf(s, 0.0f);
    }
    __syncthreads();

    for (int idx = tid; idx < NF * NE; idx += 256) {
        int f = idx >> 4, d = idx & 15;
        float s1 = 0.0f, s2 = 0.0f;
        #pragma unroll
        for (int e = 0; e < NE; e++) {
            float v = xe[f][e];
            s1 += v * Wb1[d * NE + e];
            s2 += v * Wb2[d * NE + e];
        }
        p1[f][d] = s1;
        p2[f][d] = af[f] * s2;
        xs[f][d] = af[f] * xe[f][d];
    }
    __syncthreads();

    __nv_bfloat16* ohi = a_hi + (size_t)b * K1;
    __nv_bfloat16* olo = a_lo + (size_t)b * K1;
    for (int idx = tid; idx < NPAIR * NE; idx += 256) {
        int k = idx >> 4, e = idx & 15;
        int i = ii[k], j = jj[k];
        float v1 = p1[i][e] * xe[j][e];
        float v2 = p2[i][e] * xs[j][e];
        __nv_bfloat16 h1 = __float2bfloat16(v1);
        __nv_bfloat16 h2 = __float2bfloat16(v2);
        ohi[idx] = h1;
        olo[idx] = __float2bfloat16(v1 - __bfloat162float(h1));
        ohi[idx + NPAIR * NE] = h2;
        olo[idx + NPAIR * NE] = __float2bfloat16(v2 - __bfloat162float(h2));
    }
}

// =====================================================================
// Kernel 1b: split mw0 into bf16 hi/lo (no pad; K1 % 32 == 0)
// =====================================================================
__global__ __launch_bounds__(256) void split_b(
    const float* __restrict__ w, __nv_bfloat16* __restrict__ hi,
    __nv_bfloat16* __restrict__ lo)
{
    size_t i = (size_t)blockIdx.x * 256 + threadIdx.x;
    size_t n = (size_t)HID * K1;
    if (i < n) {
        float v = w[i];
        __nv_bfloat16 h = __float2bfloat16(v);
        hi[i] = h;
        lo[i] = __float2bfloat16(v - __bfloat162float(h));
    }
}

// =====================================================================
// Kernel 1c: split 400x400 weight into padded [400][416] bf16 hi/lo
// =====================================================================
__global__ __launch_bounds__(256) void wsplit(
    const float* __restrict__ w, __nv_bfloat16* __restrict__ hi,
    __nv_bfloat16* __restrict__ lo)
{
    int idx = blockIdx.x * 256 + threadIdx.x;   // < 400*416
    int row = idx / K2P, col = idx - row * K2P;
    float v = (col < HID) ? w[row * HID + col] : 0.0f;
    __nv_bfloat16 h = __float2bfloat16(v);
    hi[idx] = h;
    lo[idx] = __float2bfloat16(v - __bfloat162float(h));
}

// =====================================================================
// Kernel: generic bf16 3-product GEMM (mma.sync + ldmatrix + cp.async)
//   out[z][m,n] (+bias) = sum_{k in seg z} A[m,k]*B[n,k]
//   CTA 128x80, BK=32, 8 warps (4m x 2n), warp 32x40
// =====================================================================
__global__ __launch_bounds__(256, 1) void gemm_bf3(
    const __nv_bfloat16* __restrict__ aH, const __nv_bfloat16* __restrict__ aL,
    const __nv_bfloat16* __restrict__ bH, const __nv_bfloat16* __restrict__ bL,
    float* __restrict__ out, const float* __restrict__ bias,
    int Kst, int ksplit)
{
    extern __shared__ char smem[];
    const uint32_t sb = smem_u32(smem);
    const int tid  = threadIdx.x;
    const int wid  = tid >> 5;
    const int lane = tid & 31;

    const int nbase = blockIdx.x * BN;
    const int mbase = blockIdx.y * BM;
    const int z     = blockIdx.z;

    const int tilesTot = Kst / BK;
    const int qt = tilesTot / ksplit, rt = tilesTot % ksplit;
    const int t0 = z * qt + (z < rt ? z : rt);
    const int T  = qt + (z < rt ? 1 : 0);

    const int wm = (wid & 3) * 32;
    const int wn = (wid >> 2) * 40;
    const int grp = lane >> 2;
    const int qd  = lane & 3;

    // ldmatrix source offsets (relative to stage base)
    const uint32_t aoff = (uint32_t)((wm + (lane & 15)) * A_ROWB + ((lane >> 4) * 16));
    const int rowB = (lane & 7) + ((lane >> 4) << 3);
    const int kB   = ((lane >> 3) & 1) * 16;
    const uint32_t boff  = (uint32_t)(OFF_BHI + (wn + rowB) * A_ROWB + kB);
    const uint32_t boff2 = (uint32_t)(OFF_BHI + (wn + 32 + (lane & 7)) * A_ROWB + kB);

    float acc[2][5][4];
    #pragma unroll
    for (int im = 0; im < 2; im++)
        #pragma unroll
        for (int in = 0; in < 5; in++)
            #pragma unroll
            for (int r = 0; r < 4; r++) acc[im][in][r] = 0.0f;

    auto load_tile = [&](int s, int t) {
        const int k0 = t * BK;
        const uint32_t st = sb + s * STAGE;
        #pragma unroll
        for (int i = 0; i < 2; i++) {                  // A: 512 16B chunks
            int idx = tid + i * 256;
            int rr = idx >> 2, ch = idx & 3;
            uint32_t dst = st + rr * A_ROWB + ch * 16;
            size_t g = (size_t)(mbase + rr) * Kst + k0 + ch * 8;
            CP_ASYNC16(dst, aH + g);
            CP_ASYNC16(dst + OFF_ALO, aL + g);
        }
        {                                              // B: 320 chunks, part 1
            int rr = tid >> 2, ch = tid & 3;
            if (tid < 320) {
                uint32_t dst = st + OFF_BHI + rr * A_ROWB + ch * 16;
                size_t g = (size_t)(nbase + rr) * Kst + k0 + ch * 8;
                CP_ASYNC16(dst, bH + g);
                CP_ASYNC16(dst + 6400, bL + g);
            }
        }
        if (tid < 64) {                                // B chunks 256..319
            int idx = tid + 256;
            int rr = idx >> 2, ch = idx & 3;
            uint32_t dst = st + OFF_BHI + rr * A_ROWB + ch * 16;
            size_t g = (size_t)(nbase + rr) * Kst + k0 + ch * 8;
            CP_ASYNC16(dst, bH + g);
            CP_ASYNC16(dst + 6400, bL + g);
        }
        CP_COMMIT();
    };

    // prologue (T >= 13 for every call site)
    load_tile(0, t0);
    load_tile(1, t0 + 1);
    load_tile(2, t0 + 2);

    for (int u = 0; u < T; ++u) {
        const int rem = T - 1 - u;
        if (rem >= 2) { CP_WAIT2(); } else if (rem == 1) { CP_WAIT1(); } else { CP_WAIT0(); }
        __syncthreads();

        if (u + 3 < T) load_tile((u + 3) & 3, t0 + u + 3);

        const uint32_t sA = sb + (u & 3) * STAGE;
        #pragma unroll
        for (int ks = 0; ks < 2; ks++) {
            const uint32_t ka = ks * 32;
            uint32_t ah[2][4], al[2][4], bh[5][2], bl[5][2];
            LDSM4(ah[0][0], ah[0][1], ah[0][2], ah[0][3], sA + aoff + ka);
            LDSM4(ah[1][0], ah[1][1], ah[1][2], ah[1][3], sA + aoff + 1280 + ka);
            LDSM4(al[0][0], al[0][1], al[0][2], al[0][3], sA + aoff + OFF_ALO + ka);
            LDSM4(al[1][0], al[1][1], al[1][2], al[1][3], sA + aoff + OFF_ALO + 1280 + ka);
            LDSM4(bh[0][0], bh[0][1], bh[1][0], bh[1][1], sA + boff + ka);
            LDSM4(bh[2][0], bh[2][1], bh[3][0], bh[3][1], sA + boff + 1280 + ka);
            LDSM2(bh[4][0], bh[4][1], sA + boff2 + ka);
            LDSM4(bl[0][0], bl[0][1], bl[1][0], bl[1][1], sA + boff + 6400 + ka);
            LDSM4(bl[2][0], bl[2][1], bl[3][0], bl[3][1], sA + boff + 6400 + 1280 + ka);
            LDSM2(bl[4][0], bl[4][1], sA + boff2 + 6400 + ka);

            #pragma unroll
            for (int im = 0; im < 2; im++)
                #pragma unroll
                for (int in = 0; in < 5; in++) {
                    mma_bf16(acc[im][in], ah[im], bh[in]);
                    mma_bf16(acc[im][in], ah[im], bl[in]);
                    mma_bf16(acc[im][in], al[im], bh[in]);
                }
        }
    }

    // epilogue
    const size_t outBase = (size_t)z * BATCH * HID;
    #pragma unroll
    for (int im = 0; im < 2; im++) {
        #pragma unroll
        for (int in = 0; in < 5; in++) {
            int row = mbase + wm + im * 16 + grp;
            int col = nbase + wn + in * 8 + qd * 2;
            float b0 = 0.f, b1 = 0.f;
            if (bias) { b0 = bias[col]; b1 = bias[col + 1]; }
            float* d = out + outBase + (size_t)row * HID + col;
            *(float2*)d = make_float2(acc[im][in][0] + b0, acc[im][in][1] + b1);
            *(float2*)(d + 8 * HID) = make_float2(acc[im][in][2] + b0, acc[im][in][3] + b1);
        }
    }
}

// =====================================================================
// reduce split-K partials + bias -> h0, with fused BN column partials
// =====================================================================
__global__ __launch_bounds__(256) void reduce_h0_stats(
    const float* __restrict__ part, const float* __restrict__ bias,
    float* __restrict__ h0, float* __restrict__ pstat)
{
    const int b = blockIdx.x;   // 0..127 (32 rows each)
    const int t = threadIdx.x;
    const int r0 = b * 32;
    const int c0 = t, c1 = t + 256;
    float s0 = 0.f, q0 = 0.f, s1 = 0.f, q1 = 0.f;
    for (int r = 0; r < 32; r++) {
        size_t base = (size_t)(r0 + r) * HID;
        float v = bias[c0];
        #pragma unroll
        for (int zz = 0; zz < KSPLIT0; zz++) v += part[(size_t)zz * BATCH * HID + base + c0];
        h0[base + c0] = v; s0 += v; q0 += v * v;
        if (c1 < HID) {
            float w = bias[c1];
            #pragma unroll
            for (int zz = 0; zz < KSPLIT0; zz++) w += part[(size_t)zz * BATCH * HID + base + c1];
            h0[base + c1] = w; s1 += w; q1 += w * w;
        }
    }
    pstat[c0 * 128 + b] = s0; pstat[SQOFF + c0 * 128 + b] = q0;
    if (c1 < HID) { pstat[c1 * 128 + b] = s1; pstat[SQOFF + c1 * 128 + b] = q1; }
}

// =====================================================================
// BN pass1 on an existing h buffer (coalesced column partials)
// =====================================================================
__global__ __launch_bounds__(256) void bn_pass1(
    const float* __restrict__ h, float* __restrict__ pstat)
{
    const int b = blockIdx.x;
    const int t = threadIdx.x;
    const int r0 = b * 32;
    const int c0 = t, c1 = t + 256;
    float s0 = 0.f, q0 = 0.f, s1 = 0.f, q1 = 0.f;
    for (int r = 0; r < 32; r++) {
        size_t base = (size_t)(r0 + r) * HID;
        float v = h[base + c0]; s0 += v; q0 += v * v;
        if (c1 < HID) { float w = h[base + c1]; s1 += w; q1 += w * w; }
    }
    pstat[c0 * 128 + b] = s0; pstat[SQOFF + c0 * 128 + b] = q0;
    if (c1 < HID) { pstat[c1 * 128 + b] = s1; pstat[SQOFF + c1 * 128 + b] = q1; }
}

// =====================================================================
// BN finalize: 128 partials per column -> folded scale/shift
// =====================================================================
__global__ __launch_bounds__(128) void stats_fin(
    const float* __restrict__ pstat, const float* __restrict__ g,
    const float* __restrict__ be, float* __restrict__ sc, float* __restrict__ sh)
{
    __shared__ float ss[128], sq[128];
    const int c = blockIdx.x, t = threadIdx.x;
    ss[t] = pstat[c * 128 + t];
    sq[t] = pstat[SQOFF + c * 128 + t];
    __syncthreads();
    for (int o = 64; o > 0; o >>= 1) {
        if (t < o) { ss[t] += ss[t + o]; sq[t] += sq[t + o]; }
        __syncthreads();
    }
    if (t == 0) {
        double mu = (double)ss[0] / BATCH;
        double var = (double)sq[0] / BATCH - mu * mu;
        if (var < 0.0) var = 0.0;
        float rstd = (float)(1.0 / sqrt(var + (double)EPS));
        float s = g[c] * rstd;
        sc[c] = s;
        sh[c] = be[c] - (float)mu * s;
    }
}

// =====================================================================
// conv_split: relu(bn(h)) -> padded bf16 hi/lo [BATCH][416]
// =====================================================================
__global__ __launch_bounds__(256) void conv_split(
    const float* __restrict__ h, const float* __restrict__ sc,
    const float* __restrict__ sh,
    __nv_bfloat16* __restrict__ hi, __nv_bfloat16* __restrict__ lo)
{
    int idx = blockIdx.x * 256 + threadIdx.x;   // < BATCH*K2P
    int row = idx / K2P, col = idx - row * K2P;
    float v = 0.0f;
    if (col < HID)
        v = fmaxf(h[(size_t)row * HID + col] * sc[col] + sh[col], 0.0f);
    __nv_bfloat16 hh = __float2bfloat16(v);
    hi[idx] = hh;
    lo[idx] = __float2bfloat16(v - __bfloat162float(hh));
}

// =====================================================================
// final dot
// =====================================================================
__global__ __launch_bounds__(256) void final_dot(
    const float* __restrict__ h, const float* __restrict__ scale,
    const float* __restrict__ shift, const float* __restrict__ w3,
    const float* __restrict__ b3, float* __restrict__ out)
{
    const int gtid = blockIdx.x * blockDim.x + threadIdx.x;
    const int warp = gtid >> 5;
    const int lane = gtid & 31;
    if (warp >= BATCH) return;
    float s = 0.0f;
    for (int k = lane; k < HID; k += 32) {
        float v = fmaxf(h[(size_t)warp * HID + k] * scale[k] + shift[k], 0.0f);
        s += v * w3[k];
    }
    #pragma unroll
    for (int off = 16; off > 0; off >>= 1)
        s += __shfl_down_sync(0xFFFFFFFFu, s, off);
    if (lane == 0) out[warp] = s + b3[0];
}

// =====================================================================
// launcher
// =====================================================================
extern "C" void kernel_launch(void* const* d_in, const int* in_sizes, int n_in,
                              void* d_out, int out_size)
{
    const int*   x    = (const int*)  d_in[0];
    const float* emb  = (const float*)d_in[1];
    const float* sw1  = (const float*)d_in[2];
    const float* sb1  = (const float*)d_in[3];
    const float* sw2  = (const float*)d_in[4];
    const float* sb2  = (const float*)d_in[5];
    const float* Wb1  = (const float*)d_in[6];
    const float* Wb2  = (const float*)d_in[7];
    const float* mw0  = (const float*)d_in[8];
    const float* mb0  = (const float*)d_in[9];
    const float* g0   = (const float*)d_in[10];
    const float* be0  = (const float*)d_in[11];
    const float* mw1  = (const float*)d_in[12];
    const float* mb1  = (const float*)d_in[13];
    const float* g1   = (const float*)d_in[14];
    const float* be1  = (const float*)d_in[15];
    const float* mw2  = (const float*)d_in[16];
    const float* mb2  = (const float*)d_in[17];
    const float* g2   = (const float*)d_in[18];
    const float* be2  = (const float*)d_in[19];
    const float* mw3  = (const float*)d_in[20];
    const float* mb3  = (const float*)d_in[21];
    float* out = (float*)d_out;

    __nv_bfloat16 *a_hi, *a_lo, *b_hi, *b_lo, *a2_hi, *a2_lo, *w2_hi, *w2_lo;
    float *part, *h0, *h1, *h2, *pstat, *sc, *sh;
    cudaGetSymbolAddress((void**)&a_hi, d_a_hi);
    cudaGetSymbolAddress((void**)&a_lo, d_a_lo);
    cudaGetSymbolAddress((void**)&b_hi, d_b_hi);
    cudaGetSymbolAddress((void**)&b_lo, d_b_lo);
    cudaGetSymbolAddress((void**)&a2_hi, d_a2_hi);
    cudaGetSymbolAddress((void**)&a2_lo, d_a2_lo);
    cudaGetSymbolAddress((void**)&w2_hi, d_w2_hi);
    cudaGetSymbolAddress((void**)&w2_lo, d_w2_lo);
    cudaGetSymbolAddress((void**)&part, d_part);
    cudaGetSymbolAddress((void**)&h0, d_h0);
    cudaGetSymbolAddress((void**)&h1, d_h1);
    cudaGetSymbolAddress((void**)&h2, d_h2);
    cudaGetSymbolAddress((void**)&pstat, d_pstat);
    cudaGetSymbolAddress((void**)&sc, d_scale);
    cudaGetSymbolAddress((void**)&sh, d_shift);

    static int smem_set = 0;
    if (!smem_set) {
        cudaFuncSetAttribute(gemm_bf3, cudaFuncAttributeMaxDynamicSharedMemorySize,
                             SMEM_G);
        smem_set = 1;
    }

    // 1) front end -> A hi/lo (bf16); mw0 split
    fuse_front<<<BATCH, 256>>>(x, emb, sw1, sb1, sw2, sb2, Wb1, Wb2, a_hi, a_lo);
    {
        size_t n = (size_t)HID * K1;
        split_b<<<(unsigned)((n + 255) / 256), 256>>>(mw0, b_hi, b_lo);
    }

    // 2) GEMM0 (split-K=8) + fused reduce/BN-partials
    {
        dim3 grid(HID / BN, BATCH / BM, KSPLIT0);   // (5, 32, 8) = 1280 CTAs
        gemm_bf3<<<grid, 256, SMEM_G>>>(a_hi, a_lo, b_hi, b_lo, part, nullptr,
                                        K1, KSPLIT0);
        reduce_h0_stats<<<128, 256>>>(part, mb0, h0, pstat);
        stats_fin<<<HID, 128>>>(pstat, g0, be0, sc + 0 * HID, sh + 0 * HID);
    }

    // 3) layer 1: conv -> gemm -> stats
    conv_split<<<BATCH * K2P / 256, 256>>>(h0, sc + 0 * HID, sh + 0 * HID, a2_hi, a2_lo);
    wsplit<<<HID * K2P / 256, 256>>>(mw1, w2_hi, w2_lo);
    {
        dim3 grid(HID / BN, BATCH / BM, 1);
        gemm_bf3<<<grid, 256, SMEM_G>>>(a2_hi, a2_lo, w2_hi, w2_lo, h1, mb1,
                                        K2P, 1);
    }
    bn_pass1<<<128, 256>>>(h1, pstat);
    stats_fin<<<HID, 128>>>(pstat, g1, be1, sc + 1 * HID, sh + 1 * HID);

    // 4) layer 2
    conv_split<<<BATCH * K2P / 256, 256>>>(h1, sc + 1 * HID, sh + 1 * HID, a2_hi, a2_lo);
    wsplit<<<HID * K2P / 256, 256>>>(mw2, w2_hi, w2_lo);
    {
        dim3 grid(HID / BN, BATCH / BM, 1);
        gemm_bf3<<<grid, 256, SMEM_G>>>(a2_hi, a2_lo, w2_hi, w2_lo, h2, mb2,
                                        K2P, 1);
    }
    bn_pass1<<<128, 256>>>(h2, pstat);
    stats_fin<<<HID, 128>>>(pstat, g2, be2, sc + 2 * HID, sh + 2 * HID);

    // 5) final dot
    final_dot<<<(BATCH * 32 + 255) / 256, 256>>>(h2, sc + 2 * HID, sh + 2 * HID,
                                                 mw3, mb3, out);
}